// round 8
// baseline (speedup 1.0000x reference)
#include <cuda_runtime.h>
#include <cstdint>

#define MARGIN 0.1f
#define RPT 32                          // rows per tile
#define TILE_FLOATS (RPT * 128)         // 4096
#define TILE_BYTES  (TILE_FLOATS * 4)   // 16384
#define LAB_BYTES   (RPT * 4)           // 128
#define NSTAGES 2
#define NUM_BLOCKS 888                  // 148 SMs * 6 CTAs

// Persistent device scratch; reset by last block each call so graph replays
// are deterministic.
__device__ double       g_total = 0.0;
__device__ unsigned int g_count = 0u;

__device__ __forceinline__ uint32_t smem_u32(const void* p) {
    return (uint32_t)__cvta_generic_to_shared(p);
}
__device__ __forceinline__ void mbar_init(uint32_t a, uint32_t cnt) {
    asm volatile("mbarrier.init.shared.b64 [%0], %1;" :: "r"(a), "r"(cnt) : "memory");
}
__device__ __forceinline__ void mbar_expect_tx(uint32_t a, uint32_t bytes) {
    asm volatile("mbarrier.arrive.expect_tx.shared.b64 _, [%0], %1;"
                 :: "r"(a), "r"(bytes) : "memory");
}
__device__ __forceinline__ void bulk_g2s(uint32_t dst, const void* src,
                                         uint32_t bytes, uint32_t mbar) {
    asm volatile(
        "cp.async.bulk.shared::cluster.global.mbarrier::complete_tx::bytes "
        "[%0], [%1], %2, [%3];"
        :: "r"(dst), "l"(src), "r"(bytes), "r"(mbar) : "memory");
}
__device__ __forceinline__ void mbar_wait(uint32_t a, uint32_t parity) {
    asm volatile(
        "{\n\t"
        ".reg .pred P;\n\t"
        "WAIT_%=:\n\t"
        "mbarrier.try_wait.parity.acquire.cta.shared::cta.b64 P, [%0], %1, 0x989680;\n\t"
        "@P bra.uni DONE_%=;\n\t"
        "bra.uni WAIT_%=;\n\t"
        "DONE_%=:\n\t"
        "}"
        :: "r"(a), "r"(parity) : "memory");
}
__device__ __forceinline__ void fence_async() {
    asm volatile("fence.proxy.async.shared::cta;" ::: "memory");
}

__global__ void __launch_bounds__(256)
margin_loss_kernel(const float* __restrict__ x,
                   const int* __restrict__ labels,   // int32 (JAX x64 disabled)
                   float* __restrict__ out,
                   int N)
{
    __shared__ __align__(128) float sdata[NSTAGES][TILE_FLOATS];
    __shared__ __align__(16)  int   slab[NSTAGES][RPT];
    __shared__ __align__(8)   unsigned long long smbar[NSTAGES];
    __shared__ float warp_sums[8];
    __shared__ bool  is_last;

    const int tid  = threadIdx.x;
    const int warp = tid >> 5;
    const int lane = tid & 31;
    const int ntiles = N / RPT;           // 8192 for N=262144

    if (tid == 0) {
        #pragma unroll
        for (int s = 0; s < NSTAGES; s++) mbar_init(smem_u32(&smbar[s]), 1);
        fence_async();
    }
    __syncthreads();

    // Prologue: fill both stages.
    if (tid == 0) {
        #pragma unroll
        for (int s = 0; s < NSTAGES; s++) {
            const int j = blockIdx.x + s * gridDim.x;
            if (j < ntiles) {
                const uint32_t mb = smem_u32(&smbar[s]);
                mbar_expect_tx(mb, TILE_BYTES + LAB_BYTES);
                bulk_g2s(smem_u32(&sdata[s][0]), x + (size_t)j * TILE_FLOATS,
                         TILE_BYTES, mb);
                bulk_g2s(smem_u32(&slab[s][0]), labels + (size_t)j * RPT,
                         LAB_BYTES, mb);
            }
        }
    }

    float wsum  = 0.0f;
    int   nrows = 0;   // rows this warp processed (for -MARGIN fixup)

    int i = 0;
    for (int j = blockIdx.x; j < ntiles; j += gridDim.x, i++) {
        const int s = i & (NSTAGES - 1);
        mbar_wait(smem_u32(&smbar[s]), (i >> 1) & 1);

        // 8 warps x 4 rows = 32 rows. Conflict-free float4 row reads;
        // label + c are smem broadcast loads (no shuffles, no gmem gather).
        const float* xs = sdata[s];
        #pragma unroll
        for (int r0 = 0; r0 < RPT / 8; r0++) {
            const int r  = warp * (RPT / 8) + r0;
            const int lb = slab[s][r];
            const float c = xs[r * 128 + lb];
            const float4 v = reinterpret_cast<const float4*>(xs + r * 128)[lane];
            const float m = MARGIN - c;
            wsum += fmaxf(m + v.x, 0.0f);
            wsum += fmaxf(m + v.y, 0.0f);
            wsum += fmaxf(m + v.z, 0.0f);
            wsum += fmaxf(m + v.w, 0.0f);
        }
        nrows += RPT / 8;

        __syncthreads();            // everyone done reading stage s
        if (tid == 0) {
            const int jn = j + NSTAGES * gridDim.x;
            if (jn < ntiles) {
                fence_async();      // order generic reads before async overwrite
                const uint32_t mb = smem_u32(&smbar[s]);
                mbar_expect_tx(mb, TILE_BYTES + LAB_BYTES);
                bulk_g2s(smem_u32(&sdata[s][0]), x + (size_t)jn * TILE_FLOATS,
                         TILE_BYTES, mb);
                bulk_g2s(smem_u32(&slab[s][0]), labels + (size_t)jn * RPT,
                         LAB_BYTES, mb);
            }
        }
    }

    // Warp reduction of everything this warp processed.
    #pragma unroll
    for (int o = 16; o > 0; o >>= 1)
        wsum += __shfl_down_sync(0xffffffffu, wsum, o);
    // Each processed row's j==label term contributed exactly MARGIN; remove.
    if (lane == 0) wsum -= MARGIN * (float)nrows;

    if (lane == 0) warp_sums[warp] = wsum;
    __syncthreads();

    if (tid == 0) {
        double bsum = 0.0;
        #pragma unroll
        for (int wi = 0; wi < 8; wi++) bsum += (double)warp_sums[wi];
        atomicAdd(&g_total, bsum);
        __threadfence();
        unsigned int t = atomicAdd(&g_count, 1u);
        is_last = (t == gridDim.x - 1);
    }
    __syncthreads();

    if (is_last && tid == 0) {
        const double total = g_total;
        // mean over N * (G-1) pairs, G = 128
        out[0] = (float)(total / ((double)N * 127.0));
        g_total = 0.0;
        g_count = 0u;
    }
}

extern "C" void kernel_launch(void* const* d_in, const int* in_sizes, int n_in,
                              void* d_out, int out_size)
{
    const float* x      = (const float*)d_in[0];
    const int*   labels = (const int*)d_in[1];
    float*       out    = (float*)d_out;

    const int N = in_sizes[1];                  // labels count = rows

    margin_loss_kernel<<<NUM_BLOCKS, 256>>>(x, labels, out, N);
}